// round 14
// baseline (speedup 1.0000x reference)
#include <cuda_runtime.h>
#include <cuda_fp16.h>
#include <cstdint>
#include <math.h>

#define N    8192
#define NW   (N/32)
#define FIN  512
#define KH   64
#define H    8
#define NCLS 16
#define NSPL1 4

__device__ uint32_t g_bits2[NW * N];       // [wordgrp][row][4 words]
__device__ __half   g_x16  [N * FIN];
__device__ __half   g_W16  [H * FIN * KH];
__device__ __half   g_Wout16[FIN * NCLS];
__device__ __half   g_Wh16 [N * FIN];
__device__ __half   g_h16  [N * FIN];
__device__ float    g_Whout[N * NCLS];
__device__ __half   g_Whout16[N * NCLS];
__device__ float    g_G1[H * N];
__device__ uint8_t  g_EF [H * N * 4];      // permuted interleaved E2/F2 (fp16)
__device__ float    g_G1o[N];
__device__ uint8_t  g_EFo[N * 4];
__device__ float    g_numO[N * NCLS];
__device__ float    g_denO[N];
__device__ float    g_part1[NSPL1 * N * FIN];
__device__ float    g_dpart1[NSPL1 * H * N];

#define SWZ128(o) ((o) ^ (((o) >> 3) & 0x70))

// attn dyn smem: sB 3x16KB | sEF 3x512B | sMask 3x2KB
#define OFF_SB   0
#define OFF_SEF  49152
#define OFF_SM   50688
#define ATT_DSMEM (56832 + 1024)
// gemm dyn smem: sA 3x16KB | sB 3x8KB
#define GOFF_SB  49152
#define GEMM_DSMEM (73728 + 1024)

__device__ __forceinline__ uint32_t smem_u32(const void* p) {
    return (uint32_t)__cvta_generic_to_shared(p);
}
__device__ __forceinline__ void cpasync16(uint32_t dst, const void* src) {
    asm volatile("cp.async.cg.shared.global [%0], [%1], 16;" :: "r"(dst), "l"(src));
}
__device__ __forceinline__ void cpcommit() {
    asm volatile("cp.async.commit_group;");
}
__device__ __forceinline__ void cpwait1() {
    asm volatile("cp.async.wait_group 1;");
}
__device__ __forceinline__ uint4 lds128(uint32_t addr) {
    uint4 v;
    asm volatile("ld.shared.v4.b32 {%0,%1,%2,%3}, [%4];"
                 : "=r"(v.x), "=r"(v.y), "=r"(v.z), "=r"(v.w) : "r"(addr));
    return v;
}
__device__ __forceinline__ void ldsm4(uint32_t& r0, uint32_t& r1, uint32_t& r2,
                                      uint32_t& r3, uint32_t a) {
    asm volatile("ldmatrix.sync.aligned.m8n8.x4.shared.b16 {%0,%1,%2,%3}, [%4];"
                 : "=r"(r0), "=r"(r1), "=r"(r2), "=r"(r3) : "r"(a));
}
__device__ __forceinline__ void ldsm4t(uint32_t& r0, uint32_t& r1, uint32_t& r2,
                                       uint32_t& r3, uint32_t a) {
    asm volatile("ldmatrix.sync.aligned.m8n8.x4.trans.shared.b16 {%0,%1,%2,%3}, [%4];"
                 : "=r"(r0), "=r"(r1), "=r"(r2), "=r"(r3) : "r"(a));
}
__device__ __forceinline__ void mma16816(float* d, uint32_t a0, uint32_t a1,
                                         uint32_t a2, uint32_t a3,
                                         uint32_t b0, uint32_t b1) {
    asm volatile(
        "mma.sync.aligned.m16n8k16.row.col.f32.f16.f16.f32 "
        "{%0,%1,%2,%3}, {%4,%5,%6,%7}, {%8,%9}, {%0,%1,%2,%3};"
        : "+f"(d[0]), "+f"(d[1]), "+f"(d[2]), "+f"(d[3])
        : "r"(a0), "r"(a1), "r"(a2), "r"(a3), "r"(b0), "r"(b1));
}
// P' = mask .* max(E2, G1*F2)
__device__ __forceinline__ uint32_t fragP2(uint32_t g1, uint32_t e2,
                                           uint32_t f2, uint32_t bits) {
    __half2 pf = __hmul2(*(__half2*)&g1, *(__half2*)&f2);
    __half2 pm = __hmax2(*(__half2*)&e2, pf);
    uint32_t m = ((bits & 1u) ? 0xFFFFu : 0u) | ((bits & 2u) ? 0xFFFF0000u : 0u);
    return (*(uint32_t*)&pm) & m;
}
// permuted EF byte offset for node j (e2 at +0, f2 at +8)
__device__ __forceinline__ uint32_t ef_off(int j) {
    return (uint32_t)((j >> 4) * 64 + ((j >> 1) & 3) * 16
                      + ((j >> 3) & 1) * 4 + (j & 1) * 2);
}

__global__ void pack_adj_kernel(const int* __restrict__ adj) {
    int warps = gridDim.x * (blockDim.x >> 5);
    int gw    = blockIdx.x * (blockDim.x >> 5) + (threadIdx.x >> 5);
    int lane  = threadIdx.x & 31;
    const int total = N * NW;
    for (int w = gw; w < total; w += warps) {
        int v = adj[(size_t)w * 32 + lane];
        unsigned m = __ballot_sync(0xffffffffu, v > 0);
        if (lane == 0) {
            int row = w >> 8, widx = w & (NW - 1);
            g_bits2[((size_t)(widx >> 2) * N + row) * 4 + (widx & 3)] = m;
        }
    }
}

__global__ void convert16_kernel(const float* __restrict__ x,
                                 const float* __restrict__ W_heads,
                                 const float* __restrict__ W_out) {
    int stride = gridDim.x * blockDim.x;
    int tid = blockIdx.x * blockDim.x + threadIdx.x;
    for (int i = tid; i < (N * FIN) / 4; i += stride) {
        float4 v = *((const float4*)x + i);
        *((__half2*)g_x16 + i * 2)     = __floats2half2_rn(v.x, v.y);
        *((__half2*)g_x16 + i * 2 + 1) = __floats2half2_rn(v.z, v.w);
    }
    for (int i = tid; i < (H * FIN * KH) / 4; i += stride) {
        float4 v = *((const float4*)W_heads + i);
        *((__half2*)g_W16 + i * 2)     = __floats2half2_rn(v.x, v.y);
        *((__half2*)g_W16 + i * 2 + 1) = __floats2half2_rn(v.z, v.w);
    }
    for (int i = tid; i < (FIN * NCLS) / 4; i += stride) {
        float4 v = *((const float4*)W_out + i);
        *((__half2*)g_Wout16 + i * 2)     = __floats2half2_rn(v.x, v.y);
        *((__half2*)g_Wout16 + i * 2 + 1) = __floats2half2_rn(v.z, v.w);
    }
}

// -------- layer-1 feature GEMM on HMMA + fused score factors --------
__global__ __launch_bounds__(256, 2) void gemm_hmma_kernel(
    const float* __restrict__ a_heads)
{
    extern __shared__ char rawsm[];
    uint32_t rawu = smem_u32(rawsm);
    uint32_t base = (rawu + 1023) & ~1023u;
    uint32_t sab = base, sbb = base + GOFF_SB;

    int t = threadIdx.x, warp = t >> 5, lane = t & 31;
    int head = blockIdx.y, i0 = blockIdx.x * 128;
    int l16 = lane & 15, lhi = lane >> 4;
    int row = warp * 16 + l16;

    const __half* asrc[4];
    uint32_t aofs_[4];
#pragma unroll
    for (int i = 0; i < 4; i++) {
        int ch = t + i * 256, r = ch >> 3, c8 = ch & 7;
        asrc[i]  = g_x16 + (size_t)(i0 + r) * FIN + c8 * 8;
        aofs_[i] = sab + SWZ128((uint32_t)(r * 128 + c8 * 16));
    }
    const __half* bsrc[2];
    uint32_t bofs_[2];
#pragma unroll
    for (int i = 0; i < 2; i++) {
        int ch = t + i * 256, r = ch >> 3, c8 = ch & 7;
        bsrc[i]  = g_W16 + (size_t)head * FIN * KH + r * KH + c8 * 8;
        bofs_[i] = sbb + SWZ128((uint32_t)(r * 128 + c8 * 16));
    }

    uint32_t alin  = (uint32_t)(row * 128 + lhi * 16);
    uint32_t bbase = (uint32_t)(l16 * 128 + lhi * 16);

    float acc[8][4];
#pragma unroll
    for (int n = 0; n < 8; n++)
#pragma unroll
        for (int q = 0; q < 4; q++) acc[n][q] = 0.f;

    auto issue = [&](int s, int buf) {
        int k0 = s * 64;
#pragma unroll
        for (int i = 0; i < 4; i++)
            cpasync16(aofs_[i] + buf * 16384, asrc[i] + k0);
#pragma unroll
        for (int i = 0; i < 2; i++)
            cpasync16(bofs_[i] + buf * 8192, bsrc[i] + (size_t)k0 * KH);
    };

    issue(0, 0); cpcommit();
    issue(1, 1); cpcommit();

    constexpr int NSTEP = FIN / 64;
#pragma unroll 1
    for (int step = 0; step < NSTEP; step++) {
        int buf = step % 3;
        cpwait1();
        __syncthreads();
        if (step + 2 < NSTEP) issue(step + 2, (step + 2) % 3);
        cpcommit();

        uint32_t pab = sab + buf * 16384;
        uint32_t pbb = sbb + buf * 8192;
#pragma unroll
        for (int kc = 0; kc < 4; kc++) {
            uint32_t a0, a1, a2, a3;
            ldsm4(a0, a1, a2, a3, pab + SWZ128(alin + kc * 32));
#pragma unroll
            for (int np = 0; np < 4; np++) {
                uint32_t b0, b1, b2, b3;
                ldsm4t(b0, b1, b2, b3, pbb + SWZ128(bbase + kc * 2048 + np * 32));
                mma16816(acc[2 * np],     a0, a1, a2, a3, b0, b1);
                mma16816(acc[2 * np + 1], a0, a1, a2, a3, b2, b3);
            }
        }
    }

    int r0 = warp * 16 + (lane >> 2), c0 = (lane & 3) * 2;
    __half* o0 = g_Wh16 + (size_t)(i0 + r0) * FIN + head * KH + c0;
    __half* o1 = o0 + 8 * FIN;
#pragma unroll
    for (int nt = 0; nt < 8; nt++) {
        *(__half2*)(o0 + nt * 8) = __floats2half2_rn(acc[nt][0], acc[nt][1]);
        *(__half2*)(o1 + nt * 8) = __floats2half2_rn(acc[nt][2], acc[nt][3]);
    }

    // ---- fused score factors ----
    {
        const float* a1 = a_heads + (size_t)head * 2 * KH;
        const float* a2 = a1 + KH;
        float v1 = 0.f, v2 = 0.f, u1 = 0.f, u2 = 0.f;
#pragma unroll
        for (int nt = 0; nt < 8; nt++) {
            int col = nt * 8 + c0;
            float a1x = a1[col], a1y = a1[col + 1];
            float a2x = a2[col], a2y = a2[col + 1];
            v1 += acc[nt][0] * a1x + acc[nt][1] * a1y;
            v2 += acc[nt][0] * a2x + acc[nt][1] * a2y;
            u1 += acc[nt][2] * a1x + acc[nt][3] * a1y;
            u2 += acc[nt][2] * a2x + acc[nt][3] * a2y;
        }
#pragma unroll
        for (int o = 1; o <= 2; o <<= 1) {
            v1 += __shfl_xor_sync(0xffffffffu, v1, o);
            v2 += __shfl_xor_sync(0xffffffffu, v2, o);
            u1 += __shfl_xor_sync(0xffffffffu, u1, o);
            u2 += __shfl_xor_sync(0xffffffffu, u2, o);
        }
        if ((lane & 3) == 0) {
            int i = i0 + r0;
            g_G1[head * N + i]      = __expf(-0.8f * v1);
            g_G1[head * N + i + 8]  = __expf(-0.8f * u1);
            // permuted EF store: rows i (hi=0) and i+8 (hi=1), same group/q/lo
            uint8_t* eb = g_EF + (size_t)head * N * 4 + ef_off(i);
            *(__half*)(eb)      = __float2half(__expf(v2));
            *(__half*)(eb + 4)  = __float2half(__expf(u2));
            *(__half*)(eb + 8)  = __float2half(__expf(0.2f * v2));
            *(__half*)(eb + 12) = __float2half(__expf(0.2f * u2));
        }
    }
}

// -------- layer-2 feature GEMM on HMMA, split-k, atomic --------
__global__ __launch_bounds__(256, 2) void gemm16_kernel()
{
    extern __shared__ char rawsm[];
    uint32_t rawu = smem_u32(rawsm);
    uint32_t base = (rawu + 1023) & ~1023u;
    uint32_t sab = base, sbb = base + GOFF_SB;

    int t = threadIdx.x, warp = t >> 5, lane = t & 31;
    int i0 = blockIdx.x * 128, kbase = blockIdx.y * 128;
    int l16 = lane & 15, lhi = lane >> 4;
    int row = warp * 16 + l16;

    const __half* asrc[4];
    uint32_t aofs_[4];
#pragma unroll
    for (int i = 0; i < 4; i++) {
        int ch = t + i * 256, r = ch >> 3, c8 = ch & 7;
        asrc[i]  = g_h16 + (size_t)(i0 + r) * FIN + kbase + c8 * 8;
        aofs_[i] = sab + SWZ128((uint32_t)(r * 128 + c8 * 16));
    }
    const __half* bsrc = nullptr;
    uint32_t bofs0 = 0;
    if (t < 128) {
        int br = t >> 1, bc = t & 1;
        bsrc = g_Wout16 + (size_t)(kbase + br) * NCLS + bc * 8;
        bofs0 = sbb + SWZ128((uint32_t)(br * 128 + bc * 16));
    }

    uint32_t alin  = (uint32_t)(row * 128 + lhi * 16);
    uint32_t bbase = (uint32_t)(l16 * 128 + lhi * 16);

    float acc[2][4];
#pragma unroll
    for (int n = 0; n < 2; n++)
#pragma unroll
        for (int q = 0; q < 4; q++) acc[n][q] = 0.f;

    auto issue = [&](int s, int buf) {
        int k0 = s * 64;
#pragma unroll
        for (int i = 0; i < 4; i++)
            cpasync16(aofs_[i] + buf * 16384, asrc[i] + k0);
        if (t < 128)
            cpasync16(bofs0 + buf * 8192, bsrc + (size_t)k0 * NCLS);
    };

    issue(0, 0); cpcommit();
    issue(1, 1); cpcommit();

#pragma unroll 1
    for (int step = 0; step < 2; step++) {
        int buf = step % 3;
        cpwait1();
        __syncthreads();
        cpcommit();

        uint32_t pab = sab + buf * 16384;
        uint32_t pbb = sbb + buf * 8192;
#pragma unroll
        for (int kc = 0; kc < 4; kc++) {
            uint32_t a0, a1, a2, a3;
            ldsm4(a0, a1, a2, a3, pab + SWZ128(alin + kc * 32));
            uint32_t b0, b1, b2, b3;
            ldsm4t(b0, b1, b2, b3, pbb + SWZ128(bbase + kc * 2048));
            mma16816(acc[0], a0, a1, a2, a3, b0, b1);
            mma16816(acc[1], a0, a1, a2, a3, b2, b3);
        }
    }

    int r0 = warp * 16 + (lane >> 2), c0 = (lane & 3) * 2;
#pragma unroll
    for (int nt = 0; nt < 2; nt++) {
        atomicAdd(&g_Whout[(i0 + r0) * NCLS + nt * 8 + c0],         acc[nt][0]);
        atomicAdd(&g_Whout[(i0 + r0) * NCLS + nt * 8 + c0 + 1],     acc[nt][1]);
        atomicAdd(&g_Whout[(i0 + r0 + 8) * NCLS + nt * 8 + c0],     acc[nt][2]);
        atomicAdd(&g_Whout[(i0 + r0 + 8) * NCLS + nt * 8 + c0 + 1], acc[nt][3]);
    }
}

__global__ void s_out_kernel(const float* __restrict__ a_out) {
    int gw = blockIdx.x * 8 + (threadIdx.x >> 5);
    int lane = threadIdx.x & 31;
    if (gw >= N) return;
    float v1 = 0.f, v2 = 0.f;
    if (lane < NCLS) {
        float w = g_Whout[(size_t)gw * NCLS + lane];
        g_Whout16[(size_t)gw * NCLS + lane] = __float2half(w);
        v1 = w * a_out[lane];
        v2 = w * a_out[NCLS + lane];
    }
#pragma unroll
    for (int o = 16; o; o >>= 1) {
        v1 += __shfl_down_sync(0xffffffffu, v1, o);
        v2 += __shfl_down_sync(0xffffffffu, v2, o);
    }
    if (lane == 0) {
        g_G1o[gw] = __expf(-0.8f * v1);
        uint8_t* eb = g_EFo + ef_off(gw);
        *(__half*)(eb)     = __float2half(__expf(v2));
        *(__half*)(eb + 8) = __float2half(__expf(0.2f * v2));
    }
}

__global__ void finalize1_kernel() {
    int idx = blockIdx.x * 256 + threadIdx.x;
    if (idx >= N * FIN) return;
    int i = idx >> 9, head = (idx & 511) >> 6;
    float num = 0.f, den = 0.f;
#pragma unroll
    for (int z = 0; z < NSPL1; z++) {
        num += g_part1[(size_t)z * N * FIN + idx];
        den += g_dpart1[(z * H + head) * N + i];
    }
    g_h16[idx] = __float2half(num / den);
}

__global__ void finalize_kernel(float* __restrict__ Out) {
    int i = blockIdx.x * 256 + threadIdx.x;
    if (i >= N * NCLS) return;
    float v = g_numO[i] / g_denO[i >> 4];
    Out[i] = (v > 0.f) ? v : expm1f(v);
}

// ============ attention: direct-fragment P-gen, interleaved EF, j-split ============
template<int NC, int NSPL, bool ATOMIC>
__global__ __launch_bounds__(256, 3) void attn_hmma(
    const float* __restrict__ G1g, const uint8_t* __restrict__ EFg,
    const __half* __restrict__ Bg, int ldb)
{
    extern __shared__ char rawsm[];
    uint32_t rawu = smem_u32(rawsm);
    uint32_t base = (rawu + 1023) & ~1023u;
    uint32_t sbb = base + OFF_SB;
    uint32_t sefb = base + OFF_SEF;
    uint32_t smb = base + OFF_SM;

    int t = threadIdx.x, warp = t >> 5, lane = t & 31;
    int head  = blockIdx.y;
    int zspl  = blockIdx.z;
    int jbase = zspl * (N / NSPL);
    constexpr int NSTEP = (N / NSPL) / 128;
    int i0 = blockIdx.x * 128;
    int bcol = (NC == 64) ? head * 64 : 0;
    int wg0 = jbase >> 7;

    int l16 = lane & 15, lhi = lane >> 4;
    int r0l = warp * 16 + (lane >> 2);
    int c0 = (lane & 3) * 2;
    uint32_t qsel = (uint32_t)((lane & 3) * 16);
    uint32_t g1r0, g1r1;
    {
        __half2 ha = __float2half2_rn(G1g[head * N + i0 + r0l]);
        __half2 hb = __float2half2_rn(G1g[head * N + i0 + r0l + 8]);
        g1r0 = *(uint32_t*)&ha;
        g1r1 = *(uint32_t*)&hb;
    }

    constexpr int CPT = (128 * NC / 8) / 256;
    const __half* bsrc0;
    uint32_t bofs0;
    {
        int br = t / (NC / 8), bc = t % (NC / 8);
        bsrc0 = Bg + (size_t)(jbase + br) * ldb + bcol + bc * 8;
        bofs0 = sbb + SWZ128((uint32_t)(br * 128 + bc * 16));
    }
    const uint8_t* efbase = EFg + ((size_t)head * N + jbase) * 4;

    uint32_t bbase = (uint32_t)(l16 * 128 + lhi * 16);
    uint32_t ones0 = (lane < 4) ? 0x3C003C00u : 0u;

    float acc[NC / 8][4];
#pragma unroll
    for (int n = 0; n < NC / 8; n++)
#pragma unroll
        for (int q = 0; q < 4; q++) acc[n][q] = 0.f;
    float accd[4] = {0.f, 0.f, 0.f, 0.f};

    const uint32_t* msrc = g_bits2 + ((size_t)wg0 * N + i0 + t) * 4;

    auto issue = [&](int s, int buf) {
        int j0 = s * 128;
#pragma unroll
        for (int i = 0; i < CPT; i++)
            cpasync16(bofs0 + buf * 16384 + i * 4096,
                      bsrc0 + (size_t)(j0 + i * 32) * ldb);
        if (t < 128)
            cpasync16(smb + buf * 2048 + t * 16, msrc + (size_t)s * N * 4);
        else if (t < 160)
            cpasync16(sefb + buf * 512 + (t - 128) * 16,
                      efbase + s * 512 + (t - 128) * 16);
    };

    issue(0, 0); cpcommit();
    if (NSTEP > 1) issue(1, 1);
    cpcommit();

#pragma unroll 1
    for (int step = 0; step < NSTEP; step++) {
        int buf = step % 3;
        cpwait1();
        __syncthreads();
        if (step + 2 < NSTEP) issue(step + 2, (step + 2) % 3);
        cpcommit();

        uint32_t pbb = sbb + buf * 16384;
        uint32_t pefb = sefb + buf * 512 + qsel;
        uint4 wq0 = lds128(smb + buf * 2048 + r0l * 16);
        uint4 wq1 = lds128(smb + buf * 2048 + r0l * 16 + 128);
#pragma unroll
        for (int kcp = 0; kcp < 4; kcp++) {
            uint32_t w0s = (&wq0.x)[kcp] >> c0;
            uint32_t w1s = (&wq1.x)[kcp] >> c0;
#pragma unroll
            for (int kh = 0; kh < 2; kh++) {
                int kc = kcp * 2 + kh;
                uint4 ef = lds128(pefb + kc * 64);
                uint32_t sh = kh * 16;
                uint32_t a0 = fragP2(g1r0, ef.x, ef.z, (w0s >> sh) & 3u);
                uint32_t a1 = fragP2(g1r1, ef.x, ef.z, (w1s >> sh) & 3u);
                uint32_t a2 = fragP2(g1r0, ef.y, ef.w, (w0s >> (sh + 8)) & 3u);
                uint32_t a3 = fragP2(g1r1, ef.y, ef.w, (w1s >> (sh + 8)) & 3u);

                mma16816(accd, a0, a1, a2, a3, ones0, ones0);
#pragma unroll
                for (int np = 0; np < NC / 16; np++) {
                    uint32_t b0, b1, b2, b3;
                    ldsm4t(b0, b1, b2, b3, pbb + SWZ128(bbase + kc * 2048 + np * 32));
                    mma16816(acc[2 * np],     a0, a1, a2, a3, b0, b1);
                    mma16816(acc[2 * np + 1], a0, a1, a2, a3, b2, b3);
                }
            }
        }
    }

    int r0 = r0l;
    if constexpr (ATOMIC) {
        if ((lane & 3) == 0) {
            atomicAdd(&g_denO[i0 + r0],     accd[0]);
            atomicAdd(&g_denO[i0 + r0 + 8], accd[2]);
        }
#pragma unroll
        for (int nt = 0; nt < NC / 8; nt++) {
            atomicAdd(&g_numO[(i0 + r0) * NCLS + nt * 8 + c0],     acc[nt][0]);
            atomicAdd(&g_numO[(i0 + r0) * NCLS + nt * 8 + c0 + 1], acc[nt][1]);
            atomicAdd(&g_numO[(i0 + r0 + 8) * NCLS + nt * 8 + c0],     acc[nt][2]);
            atomicAdd(&g_numO[(i0 + r0 + 8) * NCLS + nt * 8 + c0 + 1], acc[nt][3]);
        }
    } else {
        if ((lane & 3) == 0) {
            g_dpart1[(zspl * H + head) * N + i0 + r0]     = accd[0];
            g_dpart1[(zspl * H + head) * N + i0 + r0 + 8] = accd[2];
        }
        float* po0 = g_part1 + (size_t)zspl * N * FIN
                   + (size_t)(i0 + r0) * FIN + bcol + c0;
        float* po1 = po0 + 8 * FIN;
#pragma unroll
        for (int nt = 0; nt < NC / 8; nt++) {
            *(float2*)(po0 + nt * 8) = make_float2(acc[nt][0], acc[nt][1]);
            *(float2*)(po1 + nt * 8) = make_float2(acc[nt][2], acc[nt][3]);
        }
    }
}

extern "C" void kernel_launch(void* const* d_in, const int* in_sizes, int n_in,
                              void* d_out, int out_size)
{
    const float* x = nullptr;
    const int* adj = nullptr;
    const float *W_heads = nullptr, *a_heads = nullptr, *W_out = nullptr, *a_out = nullptr;
    for (int i = 0; i < n_in; i++) {
        switch (in_sizes[i]) {
            case N * FIN:      x       = (const float*)d_in[i]; break;
            case 67108864:     adj     = (const int*)  d_in[i]; break;
            case H * FIN * KH: W_heads = (const float*)d_in[i]; break;
            case H * 2 * KH:   a_heads = (const float*)d_in[i]; break;
            case FIN * NCLS:   W_out   = (const float*)d_in[i]; break;
            case 2 * NCLS:     a_out   = (const float*)d_in[i]; break;
        }
    }

    float *whoP, *g1P, *g1oP, *numP, *denP;
    __half *wh16P, *who16P;
    uint8_t *efP, *efoP;
    cudaGetSymbolAddress((void**)&wh16P, g_Wh16);
    cudaGetSymbolAddress((void**)&whoP,  g_Whout);
    cudaGetSymbolAddress((void**)&who16P, g_Whout16);
    cudaGetSymbolAddress((void**)&g1P,  g_G1);
    cudaGetSymbolAddress((void**)&efP,  g_EF);
    cudaGetSymbolAddress((void**)&g1oP, g_G1o);
    cudaGetSymbolAddress((void**)&efoP, g_EFo);
    cudaGetSymbolAddress((void**)&numP, g_numO);
    cudaGetSymbolAddress((void**)&denP, g_denO);

    cudaFuncSetAttribute((const void*)attn_hmma<64, NSPL1, false>,
                         cudaFuncAttributeMaxDynamicSharedMemorySize, ATT_DSMEM);
    cudaFuncSetAttribute((const void*)attn_hmma<16, 16, true>,
                         cudaFuncAttributeMaxDynamicSharedMemorySize, ATT_DSMEM);
    cudaFuncSetAttribute(gemm_hmma_kernel,
                         cudaFuncAttributeMaxDynamicSharedMemorySize, GEMM_DSMEM);
    cudaFuncSetAttribute(gemm16_kernel,
                         cudaFuncAttributeMaxDynamicSharedMemorySize, GEMM_DSMEM);

    pack_adj_kernel<<<4096, 256>>>(adj);
    convert16_kernel<<<2048, 256>>>(x, W_heads, W_out);
    gemm_hmma_kernel<<<dim3(N / 128, H), 256, GEMM_DSMEM>>>(a_heads);
    cudaMemsetAsync(numP, 0, N * NCLS * sizeof(float));
    cudaMemsetAsync(denP, 0, N * sizeof(float));
    cudaMemsetAsync(whoP, 0, N * NCLS * sizeof(float));
    attn_hmma<64, NSPL1, false><<<dim3(N / 128, H, NSPL1), 256, ATT_DSMEM>>>(
        g1P, efP, wh16P, FIN);
    finalize1_kernel<<<(N * FIN + 255) / 256, 256>>>();
    gemm16_kernel<<<dim3(N / 128, FIN / 128), 256, GEMM_DSMEM>>>();
    s_out_kernel<<<N / 8, 256>>>(a_out);
    attn_hmma<16, 16, true><<<dim3(N / 128, 1, 16), 256, ATT_DSMEM>>>(
        g1oP, efoP, who16P, NCLS);
    finalize_kernel<<<(N * NCLS + 255) / 256, 256>>>((float*)d_out);
}

// round 15
// speedup vs baseline: 1.0183x; 1.0183x over previous
#include <cuda_runtime.h>
#include <cuda_fp16.h>
#include <cstdint>
#include <math.h>

#define N    8192
#define NW   (N/32)
#define FIN  512
#define KH   64
#define H    8
#define NCLS 16
#define NSPL1 4

__device__ uint32_t g_bits2[NW * N];       // [wordgrp][row][4 words]
__device__ __half   g_x16  [N * FIN];
__device__ __half   g_W16  [H * FIN * KH];
__device__ __half   g_Wout16[FIN * NCLS];
__device__ __half   g_Wh16 [N * FIN];
__device__ __half   g_h16  [N * FIN];
__device__ float    g_Whout[N * NCLS];
__device__ __half   g_Whout16[N * NCLS];
__device__ float    g_G1[H * N];
__device__ uint8_t  g_EF [H * N * 4];      // permuted interleaved E2/F2 (fp16)
__device__ float    g_G1o[N];
__device__ uint8_t  g_EFo[N * 4];
__device__ float    g_numO[N * NCLS];
__device__ float    g_denO[N];
__device__ float    g_part1[NSPL1 * N * FIN];
__device__ float    g_dpart1[NSPL1 * H * N];

#define SWZ128(o) ((o) ^ (((o) >> 3) & 0x70))

// attn dyn smem: sB 3x16KB | sEF 3x512B | sMask 3x2KB
#define OFF_SB   0
#define OFF_SEF  49152
#define OFF_SM   50688
#define ATT_DSMEM (56832 + 1024)
// gemm dyn smem: sA 3x16KB | sB 3x8KB
#define GOFF_SB  49152
#define GEMM_DSMEM (73728 + 1024)

__device__ __forceinline__ uint32_t smem_u32(const void* p) {
    return (uint32_t)__cvta_generic_to_shared(p);
}
__device__ __forceinline__ void cpasync16(uint32_t dst, const void* src) {
    asm volatile("cp.async.cg.shared.global [%0], [%1], 16;" :: "r"(dst), "l"(src));
}
__device__ __forceinline__ void cpcommit() {
    asm volatile("cp.async.commit_group;");
}
__device__ __forceinline__ void cpwait1() {
    asm volatile("cp.async.wait_group 1;");
}
__device__ __forceinline__ uint4 lds128(uint32_t addr) {
    uint4 v;
    asm volatile("ld.shared.v4.b32 {%0,%1,%2,%3}, [%4];"
                 : "=r"(v.x), "=r"(v.y), "=r"(v.z), "=r"(v.w) : "r"(addr));
    return v;
}
__device__ __forceinline__ void ldsm4(uint32_t& r0, uint32_t& r1, uint32_t& r2,
                                      uint32_t& r3, uint32_t a) {
    asm volatile("ldmatrix.sync.aligned.m8n8.x4.shared.b16 {%0,%1,%2,%3}, [%4];"
                 : "=r"(r0), "=r"(r1), "=r"(r2), "=r"(r3) : "r"(a));
}
__device__ __forceinline__ void ldsm4t(uint32_t& r0, uint32_t& r1, uint32_t& r2,
                                       uint32_t& r3, uint32_t a) {
    asm volatile("ldmatrix.sync.aligned.m8n8.x4.trans.shared.b16 {%0,%1,%2,%3}, [%4];"
                 : "=r"(r0), "=r"(r1), "=r"(r2), "=r"(r3) : "r"(a));
}
__device__ __forceinline__ void mma16816(float* d, uint32_t a0, uint32_t a1,
                                         uint32_t a2, uint32_t a3,
                                         uint32_t b0, uint32_t b1) {
    asm volatile(
        "mma.sync.aligned.m16n8k16.row.col.f32.f16.f16.f32 "
        "{%0,%1,%2,%3}, {%4,%5,%6,%7}, {%8,%9}, {%0,%1,%2,%3};"
        : "+f"(d[0]), "+f"(d[1]), "+f"(d[2]), "+f"(d[3])
        : "r"(a0), "r"(a1), "r"(a2), "r"(a3), "r"(b0), "r"(b1));
}
// P' = mask .* max(E2, G1*F2)
__device__ __forceinline__ uint32_t fragP2(uint32_t g1, uint32_t e2,
                                           uint32_t f2, uint32_t bits) {
    __half2 pf = __hmul2(*(__half2*)&g1, *(__half2*)&f2);
    __half2 pm = __hmax2(*(__half2*)&e2, pf);
    uint32_t m = ((bits & 1u) ? 0xFFFFu : 0u) | ((bits & 2u) ? 0xFFFF0000u : 0u);
    return (*(uint32_t*)&pm) & m;
}
// permuted EF byte offset for node j (e2 at +0, f2 at +8)
__device__ __forceinline__ uint32_t ef_off(int j) {
    return (uint32_t)((j >> 4) * 64 + ((j >> 1) & 3) * 16
                      + ((j >> 3) & 1) * 4 + (j & 1) * 2);
}

__global__ void pack_adj_kernel(const int* __restrict__ adj) {
    int warps = gridDim.x * (blockDim.x >> 5);
    int gw    = blockIdx.x * (blockDim.x >> 5) + (threadIdx.x >> 5);
    int lane  = threadIdx.x & 31;
    const int total = N * NW;
    for (int w = gw; w < total; w += warps) {
        int v = adj[(size_t)w * 32 + lane];
        unsigned m = __ballot_sync(0xffffffffu, v > 0);
        if (lane == 0) {
            int row = w >> 8, widx = w & (NW - 1);
            g_bits2[((size_t)(widx >> 2) * N + row) * 4 + (widx & 3)] = m;
        }
    }
}

__global__ void convert16_kernel(const float* __restrict__ x,
                                 const float* __restrict__ W_heads,
                                 const float* __restrict__ W_out) {
    int stride = gridDim.x * blockDim.x;
    int tid = blockIdx.x * blockDim.x + threadIdx.x;
    for (int i = tid; i < (N * FIN) / 4; i += stride) {
        float4 v = *((const float4*)x + i);
        *((__half2*)g_x16 + i * 2)     = __floats2half2_rn(v.x, v.y);
        *((__half2*)g_x16 + i * 2 + 1) = __floats2half2_rn(v.z, v.w);
    }
    for (int i = tid; i < (H * FIN * KH) / 4; i += stride) {
        float4 v = *((const float4*)W_heads + i);
        *((__half2*)g_W16 + i * 2)     = __floats2half2_rn(v.x, v.y);
        *((__half2*)g_W16 + i * 2 + 1) = __floats2half2_rn(v.z, v.w);
    }
    for (int i = tid; i < (FIN * NCLS) / 4; i += stride) {
        float4 v = *((const float4*)W_out + i);
        *((__half2*)g_Wout16 + i * 2)     = __floats2half2_rn(v.x, v.y);
        *((__half2*)g_Wout16 + i * 2 + 1) = __floats2half2_rn(v.z, v.w);
    }
}

// -------- layer-1 feature GEMM on HMMA + fused score factors --------
__global__ __launch_bounds__(256, 2) void gemm_hmma_kernel(
    const float* __restrict__ a_heads)
{
    extern __shared__ char rawsm[];
    uint32_t rawu = smem_u32(rawsm);
    uint32_t base = (rawu + 1023) & ~1023u;
    uint32_t sab = base, sbb = base + GOFF_SB;

    int t = threadIdx.x, warp = t >> 5, lane = t & 31;
    int head = blockIdx.y, i0 = blockIdx.x * 128;
    int l16 = lane & 15, lhi = lane >> 4;
    int row = warp * 16 + l16;

    const __half* asrc[4];
    uint32_t aofs_[4];
#pragma unroll
    for (int i = 0; i < 4; i++) {
        int ch = t + i * 256, r = ch >> 3, c8 = ch & 7;
        asrc[i]  = g_x16 + (size_t)(i0 + r) * FIN + c8 * 8;
        aofs_[i] = sab + SWZ128((uint32_t)(r * 128 + c8 * 16));
    }
    const __half* bsrc[2];
    uint32_t bofs_[2];
#pragma unroll
    for (int i = 0; i < 2; i++) {
        int ch = t + i * 256, r = ch >> 3, c8 = ch & 7;
        bsrc[i]  = g_W16 + (size_t)head * FIN * KH + r * KH + c8 * 8;
        bofs_[i] = sbb + SWZ128((uint32_t)(r * 128 + c8 * 16));
    }

    uint32_t alin  = (uint32_t)(row * 128 + lhi * 16);
    uint32_t bbase = (uint32_t)(l16 * 128 + lhi * 16);
    // hoisted swizzled fragment offsets
    uint32_t aswz[4], bswz[4];
#pragma unroll
    for (int kc = 0; kc < 4; kc++) aswz[kc] = SWZ128(alin + kc * 32);
#pragma unroll
    for (int np = 0; np < 4; np++) bswz[np] = SWZ128(bbase + np * 32);

    float acc[8][4];
#pragma unroll
    for (int n = 0; n < 8; n++)
#pragma unroll
        for (int q = 0; q < 4; q++) acc[n][q] = 0.f;

    auto issue = [&](int s, int buf) {
        int k0 = s * 64;
#pragma unroll
        for (int i = 0; i < 4; i++)
            cpasync16(aofs_[i] + buf * 16384, asrc[i] + k0);
#pragma unroll
        for (int i = 0; i < 2; i++)
            cpasync16(bofs_[i] + buf * 8192, bsrc[i] + (size_t)k0 * KH);
    };

    issue(0, 0); cpcommit();
    issue(1, 1); cpcommit();

    constexpr int NSTEP = FIN / 64;
#pragma unroll 1
    for (int step = 0; step < NSTEP; step++) {
        int buf = step % 3;
        cpwait1();
        __syncthreads();
        if (step + 2 < NSTEP) issue(step + 2, (step + 2) % 3);
        cpcommit();

        uint32_t pab = sab + buf * 16384;
        uint32_t pbb = sbb + buf * 8192;
#pragma unroll
        for (int kc = 0; kc < 4; kc++) {
            uint32_t a0, a1, a2, a3;
            ldsm4(a0, a1, a2, a3, pab + aswz[kc]);
#pragma unroll
            for (int np = 0; np < 4; np++) {
                uint32_t b0, b1, b2, b3;
                ldsm4t(b0, b1, b2, b3, pbb + bswz[np] + kc * 2048);
                mma16816(acc[2 * np],     a0, a1, a2, a3, b0, b1);
                mma16816(acc[2 * np + 1], a0, a1, a2, a3, b2, b3);
            }
        }
    }

    int r0 = warp * 16 + (lane >> 2), c0 = (lane & 3) * 2;
    __half* o0 = g_Wh16 + (size_t)(i0 + r0) * FIN + head * KH + c0;
    __half* o1 = o0 + 8 * FIN;
#pragma unroll
    for (int nt = 0; nt < 8; nt++) {
        *(__half2*)(o0 + nt * 8) = __floats2half2_rn(acc[nt][0], acc[nt][1]);
        *(__half2*)(o1 + nt * 8) = __floats2half2_rn(acc[nt][2], acc[nt][3]);
    }

    // ---- fused score factors ----
    {
        const float* a1 = a_heads + (size_t)head * 2 * KH;
        const float* a2 = a1 + KH;
        float v1 = 0.f, v2 = 0.f, u1 = 0.f, u2 = 0.f;
#pragma unroll
        for (int nt = 0; nt < 8; nt++) {
            int col = nt * 8 + c0;
            float a1x = a1[col], a1y = a1[col + 1];
            float a2x = a2[col], a2y = a2[col + 1];
            v1 += acc[nt][0] * a1x + acc[nt][1] * a1y;
            v2 += acc[nt][0] * a2x + acc[nt][1] * a2y;
            u1 += acc[nt][2] * a1x + acc[nt][3] * a1y;
            u2 += acc[nt][2] * a2x + acc[nt][3] * a2y;
        }
#pragma unroll
        for (int o = 1; o <= 2; o <<= 1) {
            v1 += __shfl_xor_sync(0xffffffffu, v1, o);
            v2 += __shfl_xor_sync(0xffffffffu, v2, o);
            u1 += __shfl_xor_sync(0xffffffffu, u1, o);
            u2 += __shfl_xor_sync(0xffffffffu, u2, o);
        }
        if ((lane & 3) == 0) {
            int i = i0 + r0;
            g_G1[head * N + i]      = __expf(-0.8f * v1);
            g_G1[head * N + i + 8]  = __expf(-0.8f * u1);
            uint8_t* eb = g_EF + (size_t)head * N * 4 + ef_off(i);
            *(__half*)(eb)      = __float2half(__expf(v2));
            *(__half*)(eb + 4)  = __float2half(__expf(u2));
            *(__half*)(eb + 8)  = __float2half(__expf(0.2f * v2));
            *(__half*)(eb + 12) = __float2half(__expf(0.2f * u2));
        }
    }
}

// -------- layer-2 feature GEMM on HMMA, split-k, atomic --------
__global__ __launch_bounds__(256, 2) void gemm16_kernel()
{
    extern __shared__ char rawsm[];
    uint32_t rawu = smem_u32(rawsm);
    uint32_t base = (rawu + 1023) & ~1023u;
    uint32_t sab = base, sbb = base + GOFF_SB;

    int t = threadIdx.x, warp = t >> 5, lane = t & 31;
    int i0 = blockIdx.x * 128, kbase = blockIdx.y * 128;
    int l16 = lane & 15, lhi = lane >> 4;
    int row = warp * 16 + l16;

    const __half* asrc[4];
    uint32_t aofs_[4];
#pragma unroll
    for (int i = 0; i < 4; i++) {
        int ch = t + i * 256, r = ch >> 3, c8 = ch & 7;
        asrc[i]  = g_h16 + (size_t)(i0 + r) * FIN + kbase + c8 * 8;
        aofs_[i] = sab + SWZ128((uint32_t)(r * 128 + c8 * 16));
    }
    const __half* bsrc = nullptr;
    uint32_t bofs0 = 0;
    if (t < 128) {
        int br = t >> 1, bc = t & 1;
        bsrc = g_Wout16 + (size_t)(kbase + br) * NCLS + bc * 8;
        bofs0 = sbb + SWZ128((uint32_t)(br * 128 + bc * 16));
    }

    uint32_t alin  = (uint32_t)(row * 128 + lhi * 16);
    uint32_t bbase = (uint32_t)(l16 * 128 + lhi * 16);
    uint32_t aswz[4];
#pragma unroll
    for (int kc = 0; kc < 4; kc++) aswz[kc] = SWZ128(alin + kc * 32);
    uint32_t bswz0 = SWZ128(bbase);

    float acc[2][4];
#pragma unroll
    for (int n = 0; n < 2; n++)
#pragma unroll
        for (int q = 0; q < 4; q++) acc[n][q] = 0.f;

    auto issue = [&](int s, int buf) {
        int k0 = s * 64;
#pragma unroll
        for (int i = 0; i < 4; i++)
            cpasync16(aofs_[i] + buf * 16384, asrc[i] + k0);
        if (t < 128)
            cpasync16(bofs0 + buf * 8192, bsrc + (size_t)k0 * NCLS);
    };

    issue(0, 0); cpcommit();
    issue(1, 1); cpcommit();

#pragma unroll 1
    for (int step = 0; step < 2; step++) {
        int buf = step % 3;
        cpwait1();
        __syncthreads();
        cpcommit();

        uint32_t pab = sab + buf * 16384;
        uint32_t pbb = sbb + buf * 8192;
#pragma unroll
        for (int kc = 0; kc < 4; kc++) {
            uint32_t a0, a1, a2, a3;
            ldsm4(a0, a1, a2, a3, pab + aswz[kc]);
            uint32_t b0, b1, b2, b3;
            ldsm4t(b0, b1, b2, b3, pbb + bswz0 + kc * 2048);
            mma16816(acc[0], a0, a1, a2, a3, b0, b1);
            mma16816(acc[1], a0, a1, a2, a3, b2, b3);
        }
    }

    int r0 = warp * 16 + (lane >> 2), c0 = (lane & 3) * 2;
#pragma unroll
    for (int nt = 0; nt < 2; nt++) {
        atomicAdd(&g_Whout[(i0 + r0) * NCLS + nt * 8 + c0],         acc[nt][0]);
        atomicAdd(&g_Whout[(i0 + r0) * NCLS + nt * 8 + c0 + 1],     acc[nt][1]);
        atomicAdd(&g_Whout[(i0 + r0 + 8) * NCLS + nt * 8 + c0],     acc[nt][2]);
        atomicAdd(&g_Whout[(i0 + r0 + 8) * NCLS + nt * 8 + c0 + 1], acc[nt][3]);
    }
}

__global__ void s_out_kernel(const float* __restrict__ a_out) {
    int gw = blockIdx.x * 8 + (threadIdx.x >> 5);
    int lane = threadIdx.x & 31;
    if (gw >= N) return;
    float v1 = 0.f, v2 = 0.f;
    if (lane < NCLS) {
        float w = g_Whout[(size_t)gw * NCLS + lane];
        g_Whout16[(size_t)gw * NCLS + lane] = __float2half(w);
        v1 = w * a_out[lane];
        v2 = w * a_out[NCLS + lane];
    }
#pragma unroll
    for (int o = 16; o; o >>= 1) {
        v1 += __shfl_down_sync(0xffffffffu, v1, o);
        v2 += __shfl_down_sync(0xffffffffu, v2, o);
    }
    if (lane == 0) {
        g_G1o[gw] = __expf(-0.8f * v1);
        uint8_t* eb = g_EFo + ef_off(gw);
        *(__half*)(eb)     = __float2half(__expf(v2));
        *(__half*)(eb + 8) = __float2half(__expf(0.2f * v2));
    }
}

__global__ void finalize1_kernel() {
    int idx = blockIdx.x * 256 + threadIdx.x;
    if (idx >= N * FIN) return;
    int i = idx >> 9, head = (idx & 511) >> 6;
    float num = 0.f, den = 0.f;
#pragma unroll
    for (int z = 0; z < NSPL1; z++) {
        num += g_part1[(size_t)z * N * FIN + idx];
        den += g_dpart1[(z * H + head) * N + i];
    }
    g_h16[idx] = __float2half(num / den);
}

__global__ void finalize_kernel(float* __restrict__ Out) {
    int i = blockIdx.x * 256 + threadIdx.x;
    if (i >= N * NCLS) return;
    float v = g_numO[i] / g_denO[i >> 4];
    Out[i] = (v > 0.f) ? v : expm1f(v);
}

// ============ attention: direct-fragment P-gen, interleaved EF, j-split ============
template<int NC, int NSPL, bool ATOMIC>
__global__ __launch_bounds__(256, 3) void attn_hmma(
    const float* __restrict__ G1g, const uint8_t* __restrict__ EFg,
    const __half* __restrict__ Bg, int ldb)
{
    extern __shared__ char rawsm[];
    uint32_t rawu = smem_u32(rawsm);
    uint32_t base = (rawu + 1023) & ~1023u;
    uint32_t sbb = base + OFF_SB;
    uint32_t sefb = base + OFF_SEF;
    uint32_t smb = base + OFF_SM;

    int t = threadIdx.x, warp = t >> 5, lane = t & 31;
    int head  = blockIdx.y;
    int zspl  = blockIdx.z;
    int jbase = zspl * (N / NSPL);
    constexpr int NSTEP = (N / NSPL) / 128;
    int i0 = blockIdx.x * 128;
    int bcol = (NC == 64) ? head * 64 : 0;
    int wg0 = jbase >> 7;

    int l16 = lane & 15, lhi = lane >> 4;
    int r0l = warp * 16 + (lane >> 2);
    int c0 = (lane & 3) * 2;
    uint32_t qsel = (uint32_t)((lane & 3) * 16);
    uint32_t g1r0, g1r1;
    {
        __half2 ha = __float2half2_rn(G1g[head * N + i0 + r0l]);
        __half2 hb = __float2half2_rn(G1g[head * N + i0 + r0l + 8]);
        g1r0 = *(uint32_t*)&ha;
        g1r1 = *(uint32_t*)&hb;
    }

    constexpr int CPT = (128 * NC / 8) / 256;
    const __half* bsrc0;
    uint32_t bofs0;
    {
        int br = t / (NC / 8), bc = t % (NC / 8);
        bsrc0 = Bg + (size_t)(jbase + br) * ldb + bcol + bc * 8;
        bofs0 = sbb + SWZ128((uint32_t)(br * 128 + bc * 16));
    }
    const uint8_t* efbase = EFg + ((size_t)head * N + jbase) * 4;

    // hoisted swizzled B-fragment offsets (np-indexed; kc*2048 stays linear)
    uint32_t bbase = (uint32_t)(l16 * 128 + lhi * 16);
    uint32_t bswz[NC / 16];
#pragma unroll
    for (int np = 0; np < NC / 16; np++) bswz[np] = SWZ128(bbase + np * 32);
    uint32_t ones0 = (lane < 4) ? 0x3C003C00u : 0u;

    float acc[NC / 8][4];
#pragma unroll
    for (int n = 0; n < NC / 8; n++)
#pragma unroll
        for (int q = 0; q < 4; q++) acc[n][q] = 0.f;
    float accd[4] = {0.f, 0.f, 0.f, 0.f};

    const uint32_t* msrc = g_bits2 + ((size_t)wg0 * N + i0 + t) * 4;

    auto issue = [&](int s, int buf) {
        int j0 = s * 128;
#pragma unroll
        for (int i = 0; i < CPT; i++)
            cpasync16(bofs0 + buf * 16384 + i * 4096,
                      bsrc0 + (size_t)(j0 + i * 32) * ldb);
        if (t < 128)
            cpasync16(smb + buf * 2048 + t * 16, msrc + (size_t)s * N * 4);
        else if (t < 160)
            cpasync16(sefb + buf * 512 + (t - 128) * 16,
                      efbase + s * 512 + (t - 128) * 16);
    };

    issue(0, 0); cpcommit();
    if (NSTEP > 1) issue(1, 1);
    cpcommit();

#pragma unroll 1
    for (int step = 0; step < NSTEP; step++) {
        int buf = step % 3;
        cpwait1();
        __syncthreads();
        if (step + 2 < NSTEP) issue(step + 2, (step + 2) % 3);
        cpcommit();

        uint32_t pbb = sbb + buf * 16384;
        uint32_t pefb = sefb + buf * 512 + qsel;
        uint4 wq0 = lds128(smb + buf * 2048 + r0l * 16);
        uint4 wq1 = lds128(smb + buf * 2048 + r0l * 16 + 128);
#pragma unroll
        for (int kcp = 0; kcp < 4; kcp++) {
            uint32_t w0s = (&wq0.x)[kcp] >> c0;
            uint32_t w1s = (&wq1.x)[kcp] >> c0;
#pragma unroll
            for (int kh = 0; kh < 2; kh++) {
                int kc = kcp * 2 + kh;
                uint4 ef = lds128(pefb + kc * 64);
                uint32_t sh = kh * 16;
                uint32_t a0 = fragP2(g1r0, ef.x, ef.z, (w0s >> sh) & 3u);
                uint32_t a1 = fragP2(g1r1, ef.x, ef.z, (w1s >> sh) & 3u);
                uint32_t a2 = fragP2(g1r0, ef.y, ef.w, (w0s >> (sh + 8)) & 3u);
                uint32_t a3 = fragP2(g1r1, ef.y, ef.w, (w1s >> (sh + 8)) & 3u);

                mma16816(accd, a0, a1, a2, a3, ones0, ones0);
#pragma unroll
                for (int np = 0; np < NC / 16; np++) {
                    uint32_t b0, b1, b2, b3;
                    ldsm4t(b0, b1, b2, b3, pbb + bswz[np] + kc * 2048);
                    mma16816(acc[2 * np],     a0, a1, a2, a3, b0, b1);
                    mma16816(acc[2 * np + 1], a0, a1, a2, a3, b2, b3);
                }
            }
        }
    }

    int r0 = r0l;
    if constexpr (ATOMIC) {
        if ((lane & 3) == 0) {
            atomicAdd(&g_denO[i0 + r0],     accd[0]);
            atomicAdd(&g_denO[i0 + r0 + 8], accd[2]);
        }
#pragma unroll
        for (int nt = 0; nt < NC / 8; nt++) {
            atomicAdd(&g_numO[(i0 + r0) * NCLS + nt * 8 + c0],     acc[nt][0]);
            atomicAdd(&g_numO[(i0 + r0) * NCLS + nt * 8 + c0 + 1], acc[nt][1]);
            atomicAdd(&g_numO[(i0 + r0 + 8) * NCLS + nt * 8 + c0],     acc[nt][2]);
            atomicAdd(&g_numO[(i0 + r0 + 8) * NCLS + nt * 8 + c0 + 1], acc[nt][3]);
        }
    } else {
        if ((lane & 3) == 0) {
            g_dpart1[(zspl * H + head) * N + i0 + r0]     = accd[0];
            g_dpart1[(zspl * H + head) * N + i0 + r0 + 8] = accd[2];
        }
        float* po0 = g_part1 + (size_t)zspl * N * FIN
                   + (size_t)(i0 + r0) * FIN + bcol + c0;
        float* po1 = po0 + 8 * FIN;
#pragma unroll
        for (int nt = 0; nt < NC / 8; nt++) {
            *(float2*)(po0 + nt * 8) = make_float2(acc[nt][0], acc[nt][1]);
            *(float2*)(po1 + nt * 8) = make_float2(acc[nt][2], acc[nt][3]);
        }
    }
}

extern "C" void kernel_launch(void* const* d_in, const int* in_sizes, int n_in,
                              void* d_out, int out_size)
{
    const float* x = nullptr;
    const int* adj = nullptr;
    const float *W_heads = nullptr, *a_heads = nullptr, *W_out = nullptr, *a_out = nullptr;
    for (int i = 0; i < n_in; i++) {
        switch (in_sizes[i]) {
            case N * FIN:      x       = (const float*)d_in[i]; break;
            case 67108864:     adj     = (const int*)  d_in[i]; break;
            case H * FIN * KH: W_heads = (const float*)d_in[i]; break;
            case H * 2 * KH:   a_heads = (const float*)d_in[i]; break;
            case FIN * NCLS:   W_out   = (const float*)d_in[i]; break;
            case 2 * NCLS:     a_out   = (const float*)d_in[i]; break;
        }
    }

    float *whoP, *g1P, *g1oP, *numP, *denP;
    __half *wh16P, *who16P;
    uint8_t *efP, *efoP;
    cudaGetSymbolAddress((void**)&wh16P, g_Wh16);
    cudaGetSymbolAddress((void**)&whoP,  g_Whout);
    cudaGetSymbolAddress((void**)&who16P, g_Whout16);
    cudaGetSymbolAddress((void**)&g1P,  g_G1);
    cudaGetSymbolAddress((void**)&efP,  g_EF);
    cudaGetSymbolAddress((void**)&g1oP, g_G1o);
    cudaGetSymbolAddress((void**)&efoP, g_EFo);
    cudaGetSymbolAddress((void**)&numP, g_numO);
    cudaGetSymbolAddress((void**)&denP, g_denO);

    cudaFuncSetAttribute((const void*)attn_hmma<64, NSPL1, false>,
                         cudaFuncAttributeMaxDynamicSharedMemorySize, ATT_DSMEM);
    cudaFuncSetAttribute((const void*)attn_hmma<16, 16, true>,
                         cudaFuncAttributeMaxDynamicSharedMemorySize, ATT_DSMEM);
    cudaFuncSetAttribute(gemm_hmma_kernel,
                         cudaFuncAttributeMaxDynamicSharedMemorySize, GEMM_DSMEM);
    cudaFuncSetAttribute(gemm16_kernel,
                         cudaFuncAttributeMaxDynamicSharedMemorySize, GEMM_DSMEM);

    pack_adj_kernel<<<4096, 256>>>(adj);
    convert16_kernel<<<2048, 256>>>(x, W_heads, W_out);
    gemm_hmma_kernel<<<dim3(N / 128, H), 256, GEMM_DSMEM>>>(a_heads);
    cudaMemsetAsync(numP, 0, N * NCLS * sizeof(float));
    cudaMemsetAsync(denP, 0, N * sizeof(float));
    cudaMemsetAsync(whoP, 0, N * NCLS * sizeof(float));
    attn_hmma<64, NSPL1, false><<<dim3(N / 128, H, NSPL1), 256, ATT_DSMEM>>>(
        g1P, efP, wh16P, FIN);
    finalize1_kernel<<<(N * FIN + 255) / 256, 256>>>();
    gemm16_kernel<<<dim3(N / 128, FIN / 128), 256, GEMM_DSMEM>>>();
    s_out_kernel<<<N / 8, 256>>>(a_out);
    attn_hmma<16, 16, true><<<dim3(N / 128, 1, 16), 256, ATT_DSMEM>>>(
        g1oP, efoP, who16P, NCLS);
    finalize_kernel<<<(N * NCLS + 255) / 256, 256>>>((float*)d_out);
}

// round 16
// speedup vs baseline: 1.0559x; 1.0369x over previous
#include <cuda_runtime.h>
#include <cuda_fp16.h>
#include <cstdint>
#include <math.h>

#define N    8192
#define NW   (N/32)
#define FIN  512
#define KH   64
#define H    8
#define NCLS 16
#define NSPL1 4

__device__ uint32_t g_bits2[NW * N];       // [wordgrp][row][4 words]
__device__ __half   g_x16  [N * FIN];
__device__ __half   g_W16  [H * FIN * KH];
__device__ __half   g_Wout16[FIN * NCLS];
__device__ __half   g_Wh16 [N * FIN];
__device__ __half   g_h16  [N * FIN];
__device__ float    g_Whout[N * NCLS];
__device__ __half   g_Whout16[N * NCLS];
__device__ float    g_G1[H * N];
__device__ uint8_t  g_EF [H * N * 4];      // permuted interleaved E2/F2 (fp16)
__device__ float    g_G1o[N];
__device__ uint8_t  g_EFo[N * 4];
__device__ float    g_numO[N * NCLS];
__device__ float    g_denO[N];
__device__ float    g_part1[NSPL1 * N * FIN];
__device__ float    g_dpart1[NSPL1 * H * N];

#define SWZ128(o) ((o) ^ (((o) >> 3) & 0x70))

// attn dyn smem (RG=2 max): sB 3x16KB | sEF 3x512B | sMask 3x(2KB*RG)
#define OFF_SB   0
#define OFF_SEF  49152
#define OFF_SM   50688
#define ATT_DSMEM (62976 + 1024)
// gemm dyn smem: sA 3x16KB | sB 3x8KB
#define GOFF_SB  49152
#define GEMM_DSMEM (73728 + 1024)

__device__ __forceinline__ uint32_t smem_u32(const void* p) {
    return (uint32_t)__cvta_generic_to_shared(p);
}
__device__ __forceinline__ void cpasync16(uint32_t dst, const void* src) {
    asm volatile("cp.async.cg.shared.global [%0], [%1], 16;" :: "r"(dst), "l"(src));
}
__device__ __forceinline__ void cpcommit() {
    asm volatile("cp.async.commit_group;");
}
__device__ __forceinline__ void cpwait1() {
    asm volatile("cp.async.wait_group 1;");
}
__device__ __forceinline__ uint4 lds128(uint32_t addr) {
    uint4 v;
    asm volatile("ld.shared.v4.b32 {%0,%1,%2,%3}, [%4];"
                 : "=r"(v.x), "=r"(v.y), "=r"(v.z), "=r"(v.w) : "r"(addr));
    return v;
}
__device__ __forceinline__ void ldsm4(uint32_t& r0, uint32_t& r1, uint32_t& r2,
                                      uint32_t& r3, uint32_t a) {
    asm volatile("ldmatrix.sync.aligned.m8n8.x4.shared.b16 {%0,%1,%2,%3}, [%4];"
                 : "=r"(r0), "=r"(r1), "=r"(r2), "=r"(r3) : "r"(a));
}
__device__ __forceinline__ void ldsm4t(uint32_t& r0, uint32_t& r1, uint32_t& r2,
                                       uint32_t& r3, uint32_t a) {
    asm volatile("ldmatrix.sync.aligned.m8n8.x4.trans.shared.b16 {%0,%1,%2,%3}, [%4];"
                 : "=r"(r0), "=r"(r1), "=r"(r2), "=r"(r3) : "r"(a));
}
__device__ __forceinline__ void mma16816(float* d, uint32_t a0, uint32_t a1,
                                         uint32_t a2, uint32_t a3,
                                         uint32_t b0, uint32_t b1) {
    asm volatile(
        "mma.sync.aligned.m16n8k16.row.col.f32.f16.f16.f32 "
        "{%0,%1,%2,%3}, {%4,%5,%6,%7}, {%8,%9}, {%0,%1,%2,%3};"
        : "+f"(d[0]), "+f"(d[1]), "+f"(d[2]), "+f"(d[3])
        : "r"(a0), "r"(a1), "r"(a2), "r"(a3), "r"(b0), "r"(b1));
}
// P' = mask .* max(E2, G1*F2)
__device__ __forceinline__ uint32_t fragP2(uint32_t g1, uint32_t e2,
                                           uint32_t f2, uint32_t bits) {
    __half2 pf = __hmul2(*(__half2*)&g1, *(__half2*)&f2);
    __half2 pm = __hmax2(*(__half2*)&e2, pf);
    uint32_t m = ((bits & 1u) ? 0xFFFFu : 0u) | ((bits & 2u) ? 0xFFFF0000u : 0u);
    return (*(uint32_t*)&pm) & m;
}
// permuted EF byte offset for node j (e2 at +0, f2 at +8)
__device__ __forceinline__ uint32_t ef_off(int j) {
    return (uint32_t)((j >> 4) * 64 + ((j >> 1) & 3) * 16
                      + ((j >> 3) & 1) * 4 + (j & 1) * 2);
}

__global__ void pack_adj_kernel(const int* __restrict__ adj) {
    int warps = gridDim.x * (blockDim.x >> 5);
    int gw    = blockIdx.x * (blockDim.x >> 5) + (threadIdx.x >> 5);
    int lane  = threadIdx.x & 31;
    const int total = N * NW;
    for (int w = gw; w < total; w += warps) {
        int v = adj[(size_t)w * 32 + lane];
        unsigned m = __ballot_sync(0xffffffffu, v > 0);
        if (lane == 0) {
            int row = w >> 8, widx = w & (NW - 1);
            g_bits2[((size_t)(widx >> 2) * N + row) * 4 + (widx & 3)] = m;
        }
    }
}

__global__ void convert16_kernel(const float* __restrict__ x,
                                 const float* __restrict__ W_heads,
                                 const float* __restrict__ W_out) {
    int stride = gridDim.x * blockDim.x;
    int tid = blockIdx.x * blockDim.x + threadIdx.x;
    for (int i = tid; i < (N * FIN) / 4; i += stride) {
        float4 v = *((const float4*)x + i);
        *((__half2*)g_x16 + i * 2)     = __floats2half2_rn(v.x, v.y);
        *((__half2*)g_x16 + i * 2 + 1) = __floats2half2_rn(v.z, v.w);
    }
    for (int i = tid; i < (H * FIN * KH) / 4; i += stride) {
        float4 v = *((const float4*)W_heads + i);
        *((__half2*)g_W16 + i * 2)     = __floats2half2_rn(v.x, v.y);
        *((__half2*)g_W16 + i * 2 + 1) = __floats2half2_rn(v.z, v.w);
    }
    for (int i = tid; i < (FIN * NCLS) / 4; i += stride) {
        float4 v = *((const float4*)W_out + i);
        *((__half2*)g_Wout16 + i * 2)     = __floats2half2_rn(v.x, v.y);
        *((__half2*)g_Wout16 + i * 2 + 1) = __floats2half2_rn(v.z, v.w);
    }
}

// -------- layer-1 feature GEMM on HMMA + fused score factors --------
__global__ __launch_bounds__(256, 2) void gemm_hmma_kernel(
    const float* __restrict__ a_heads)
{
    extern __shared__ char rawsm[];
    uint32_t rawu = smem_u32(rawsm);
    uint32_t base = (rawu + 1023) & ~1023u;
    uint32_t sab = base, sbb = base + GOFF_SB;

    int t = threadIdx.x, warp = t >> 5, lane = t & 31;
    int head = blockIdx.y, i0 = blockIdx.x * 128;
    int l16 = lane & 15, lhi = lane >> 4;
    int row = warp * 16 + l16;

    const __half* asrc[4];
    uint32_t aofs_[4];
#pragma unroll
    for (int i = 0; i < 4; i++) {
        int ch = t + i * 256, r = ch >> 3, c8 = ch & 7;
        asrc[i]  = g_x16 + (size_t)(i0 + r) * FIN + c8 * 8;
        aofs_[i] = sab + SWZ128((uint32_t)(r * 128 + c8 * 16));
    }
    const __half* bsrc[2];
    uint32_t bofs_[2];
#pragma unroll
    for (int i = 0; i < 2; i++) {
        int ch = t + i * 256, r = ch >> 3, c8 = ch & 7;
        bsrc[i]  = g_W16 + (size_t)head * FIN * KH + r * KH + c8 * 8;
        bofs_[i] = sbb + SWZ128((uint32_t)(r * 128 + c8 * 16));
    }

    uint32_t alin  = (uint32_t)(row * 128 + lhi * 16);
    uint32_t bbase = (uint32_t)(l16 * 128 + lhi * 16);
    uint32_t aswz[4], bswz[4];
#pragma unroll
    for (int kc = 0; kc < 4; kc++) aswz[kc] = SWZ128(alin + kc * 32);
#pragma unroll
    for (int np = 0; np < 4; np++) bswz[np] = SWZ128(bbase + np * 32);

    float acc[8][4];
#pragma unroll
    for (int n = 0; n < 8; n++)
#pragma unroll
        for (int q = 0; q < 4; q++) acc[n][q] = 0.f;

    auto issue = [&](int s, int buf) {
        int k0 = s * 64;
#pragma unroll
        for (int i = 0; i < 4; i++)
            cpasync16(aofs_[i] + buf * 16384, asrc[i] + k0);
#pragma unroll
        for (int i = 0; i < 2; i++)
            cpasync16(bofs_[i] + buf * 8192, bsrc[i] + (size_t)k0 * KH);
    };

    issue(0, 0); cpcommit();
    issue(1, 1); cpcommit();

    constexpr int NSTEP = FIN / 64;
#pragma unroll 1
    for (int step = 0; step < NSTEP; step++) {
        int buf = step % 3;
        cpwait1();
        __syncthreads();
        if (step + 2 < NSTEP) issue(step + 2, (step + 2) % 3);
        cpcommit();

        uint32_t pab = sab + buf * 16384;
        uint32_t pbb = sbb + buf * 8192;
#pragma unroll
        for (int kc = 0; kc < 4; kc++) {
            uint32_t a0, a1, a2, a3;
            ldsm4(a0, a1, a2, a3, pab + aswz[kc]);
#pragma unroll
            for (int np = 0; np < 4; np++) {
                uint32_t b0, b1, b2, b3;
                ldsm4t(b0, b1, b2, b3, pbb + bswz[np] + kc * 2048);
                mma16816(acc[2 * np],     a0, a1, a2, a3, b0, b1);
                mma16816(acc[2 * np + 1], a0, a1, a2, a3, b2, b3);
            }
        }
    }

    int r0 = warp * 16 + (lane >> 2), c0 = (lane & 3) * 2;
    __half* o0 = g_Wh16 + (size_t)(i0 + r0) * FIN + head * KH + c0;
    __half* o1 = o0 + 8 * FIN;
#pragma unroll
    for (int nt = 0; nt < 8; nt++) {
        *(__half2*)(o0 + nt * 8) = __floats2half2_rn(acc[nt][0], acc[nt][1]);
        *(__half2*)(o1 + nt * 8) = __floats2half2_rn(acc[nt][2], acc[nt][3]);
    }

    // ---- fused score factors ----
    {
        const float* a1 = a_heads + (size_t)head * 2 * KH;
        const float* a2 = a1 + KH;
        float v1 = 0.f, v2 = 0.f, u1 = 0.f, u2 = 0.f;
#pragma unroll
        for (int nt = 0; nt < 8; nt++) {
            int col = nt * 8 + c0;
            float a1x = a1[col], a1y = a1[col + 1];
            float a2x = a2[col], a2y = a2[col + 1];
            v1 += acc[nt][0] * a1x + acc[nt][1] * a1y;
            v2 += acc[nt][0] * a2x + acc[nt][1] * a2y;
            u1 += acc[nt][2] * a1x + acc[nt][3] * a1y;
            u2 += acc[nt][2] * a2x + acc[nt][3] * a2y;
        }
#pragma unroll
        for (int o = 1; o <= 2; o <<= 1) {
            v1 += __shfl_xor_sync(0xffffffffu, v1, o);
            v2 += __shfl_xor_sync(0xffffffffu, v2, o);
            u1 += __shfl_xor_sync(0xffffffffu, u1, o);
            u2 += __shfl_xor_sync(0xffffffffu, u2, o);
        }
        if ((lane & 3) == 0) {
            int i = i0 + r0;
            g_G1[head * N + i]      = __expf(-0.8f * v1);
            g_G1[head * N + i + 8]  = __expf(-0.8f * u1);
            uint8_t* eb = g_EF + (size_t)head * N * 4 + ef_off(i);
            *(__half*)(eb)      = __float2half(__expf(v2));
            *(__half*)(eb + 4)  = __float2half(__expf(u2));
            *(__half*)(eb + 8)  = __float2half(__expf(0.2f * v2));
            *(__half*)(eb + 12) = __float2half(__expf(0.2f * u2));
        }
    }
}

// -------- layer-2 feature GEMM on HMMA, split-k, atomic --------
__global__ __launch_bounds__(256, 2) void gemm16_kernel()
{
    extern __shared__ char rawsm[];
    uint32_t rawu = smem_u32(rawsm);
    uint32_t base = (rawu + 1023) & ~1023u;
    uint32_t sab = base, sbb = base + GOFF_SB;

    int t = threadIdx.x, warp = t >> 5, lane = t & 31;
    int i0 = blockIdx.x * 128, kbase = blockIdx.y * 128;
    int l16 = lane & 15, lhi = lane >> 4;
    int row = warp * 16 + l16;

    const __half* asrc[4];
    uint32_t aofs_[4];
#pragma unroll
    for (int i = 0; i < 4; i++) {
        int ch = t + i * 256, r = ch >> 3, c8 = ch & 7;
        asrc[i]  = g_h16 + (size_t)(i0 + r) * FIN + kbase + c8 * 8;
        aofs_[i] = sab + SWZ128((uint32_t)(r * 128 + c8 * 16));
    }
    const __half* bsrc = nullptr;
    uint32_t bofs0 = 0;
    if (t < 128) {
        int br = t >> 1, bc = t & 1;
        bsrc = g_Wout16 + (size_t)(kbase + br) * NCLS + bc * 8;
        bofs0 = sbb + SWZ128((uint32_t)(br * 128 + bc * 16));
    }

    uint32_t alin  = (uint32_t)(row * 128 + lhi * 16);
    uint32_t bbase = (uint32_t)(l16 * 128 + lhi * 16);
    uint32_t aswz[4];
#pragma unroll
    for (int kc = 0; kc < 4; kc++) aswz[kc] = SWZ128(alin + kc * 32);
    uint32_t bswz0 = SWZ128(bbase);

    float acc[2][4];
#pragma unroll
    for (int n = 0; n < 2; n++)
#pragma unroll
        for (int q = 0; q < 4; q++) acc[n][q] = 0.f;

    auto issue = [&](int s, int buf) {
        int k0 = s * 64;
#pragma unroll
        for (int i = 0; i < 4; i++)
            cpasync16(aofs_[i] + buf * 16384, asrc[i] + k0);
        if (t < 128)
            cpasync16(bofs0 + buf * 8192, bsrc + (size_t)k0 * NCLS);
    };

    issue(0, 0); cpcommit();
    issue(1, 1); cpcommit();

#pragma unroll 1
    for (int step = 0; step < 2; step++) {
        int buf = step % 3;
        cpwait1();
        __syncthreads();
        cpcommit();

        uint32_t pab = sab + buf * 16384;
        uint32_t pbb = sbb + buf * 8192;
#pragma unroll
        for (int kc = 0; kc < 4; kc++) {
            uint32_t a0, a1, a2, a3;
            ldsm4(a0, a1, a2, a3, pab + aswz[kc]);
            uint32_t b0, b1, b2, b3;
            ldsm4t(b0, b1, b2, b3, pbb + bswz0 + kc * 2048);
            mma16816(acc[0], a0, a1, a2, a3, b0, b1);
            mma16816(acc[1], a0, a1, a2, a3, b2, b3);
        }
    }

    int r0 = warp * 16 + (lane >> 2), c0 = (lane & 3) * 2;
#pragma unroll
    for (int nt = 0; nt < 2; nt++) {
        atomicAdd(&g_Whout[(i0 + r0) * NCLS + nt * 8 + c0],         acc[nt][0]);
        atomicAdd(&g_Whout[(i0 + r0) * NCLS + nt * 8 + c0 + 1],     acc[nt][1]);
        atomicAdd(&g_Whout[(i0 + r0 + 8) * NCLS + nt * 8 + c0],     acc[nt][2]);
        atomicAdd(&g_Whout[(i0 + r0 + 8) * NCLS + nt * 8 + c0 + 1], acc[nt][3]);
    }
}

__global__ void s_out_kernel(const float* __restrict__ a_out) {
    int gw = blockIdx.x * 8 + (threadIdx.x >> 5);
    int lane = threadIdx.x & 31;
    if (gw >= N) return;
    float v1 = 0.f, v2 = 0.f;
    if (lane < NCLS) {
        float w = g_Whout[(size_t)gw * NCLS + lane];
        g_Whout16[(size_t)gw * NCLS + lane] = __float2half(w);
        v1 = w * a_out[lane];
        v2 = w * a_out[NCLS + lane];
    }
#pragma unroll
    for (int o = 16; o; o >>= 1) {
        v1 += __shfl_down_sync(0xffffffffu, v1, o);
        v2 += __shfl_down_sync(0xffffffffu, v2, o);
    }
    if (lane == 0) {
        g_G1o[gw] = __expf(-0.8f * v1);
        uint8_t* eb = g_EFo + ef_off(gw);
        *(__half*)(eb)     = __float2half(__expf(v2));
        *(__half*)(eb + 8) = __float2half(__expf(0.2f * v2));
    }
}

__global__ void finalize1_kernel() {
    int idx = blockIdx.x * 256 + threadIdx.x;
    if (idx >= N * FIN) return;
    int i = idx >> 9, head = (idx & 511) >> 6;
    float num = 0.f, den = 0.f;
#pragma unroll
    for (int z = 0; z < NSPL1; z++) {
        num += g_part1[(size_t)z * N * FIN + idx];
        den += g_dpart1[(z * H + head) * N + i];
    }
    g_h16[idx] = __float2half(num / den);
}

__global__ void finalize_kernel(float* __restrict__ Out) {
    int i = blockIdx.x * 256 + threadIdx.x;
    if (i >= N * NCLS) return;
    float v = g_numO[i] / g_denO[i >> 4];
    Out[i] = (v > 0.f) ? v : expm1f(v);
}

// ===== attention: direct-fragment P-gen, RG row-groups/warp, j-split =====
template<int NC, int RG, int NSPL, bool ATOMIC>
__global__ __launch_bounds__(256, (RG == 2 ? 2 : 3)) void attn_hmma(
    const float* __restrict__ G1g, const uint8_t* __restrict__ EFg,
    const __half* __restrict__ Bg, int ldb)
{
    extern __shared__ char rawsm[];
    uint32_t rawu = smem_u32(rawsm);
    uint32_t base = (rawu + 1023) & ~1023u;
    uint32_t sbb = base + OFF_SB;
    uint32_t sefb = base + OFF_SEF;
    uint32_t smb = base + OFF_SM;
    constexpr int MSKSZ = 2048 * RG;          // mask bytes per buffer

    int t = threadIdx.x, warp = t >> 5, lane = t & 31;
    int head  = blockIdx.y;
    int zspl  = blockIdx.z;
    int jbase = zspl * (N / NSPL);
    constexpr int NSTEP = (N / NSPL) / 128;
    int i0 = blockIdx.x * (128 * RG);
    int bcol = (NC == 64) ? head * 64 : 0;
    int wg0 = jbase >> 7;

    int l16 = lane & 15, lhi = lane >> 4;
    int rq = lane >> 2;                       // quad row within 8
    int c0 = (lane & 3) * 2;
    uint32_t qsel = (uint32_t)((lane & 3) * 16);
    uint32_t g1a[RG], g1b[RG];
#pragma unroll
    for (int rg = 0; rg < RG; rg++) {
        int rr = i0 + warp * 16 * RG + rg * 16 + rq;
        __half2 ha = __float2half2_rn(G1g[head * N + rr]);
        __half2 hb = __float2half2_rn(G1g[head * N + rr + 8]);
        g1a[rg] = *(uint32_t*)&ha;
        g1b[rg] = *(uint32_t*)&hb;
    }

    constexpr int CPT = (128 * NC / 8) / 256;
    const __half* bsrc0;
    uint32_t bofs0;
    {
        int br = t / (NC / 8), bc = t % (NC / 8);
        bsrc0 = Bg + (size_t)(jbase + br) * ldb + bcol + bc * 8;
        bofs0 = sbb + SWZ128((uint32_t)(br * 128 + bc * 16));
    }
    const uint8_t* efbase = EFg + ((size_t)head * N + jbase) * 4;

    uint32_t bbase = (uint32_t)(l16 * 128 + lhi * 16);
    uint32_t bswz[NC / 16];
#pragma unroll
    for (int np = 0; np < NC / 16; np++) bswz[np] = SWZ128(bbase + np * 32);
    uint32_t ones0 = (lane < 4) ? 0x3C003C00u : 0u;

    float acc[RG][NC / 8][4];
#pragma unroll
    for (int rg = 0; rg < RG; rg++)
#pragma unroll
        for (int n = 0; n < NC / 8; n++)
#pragma unroll
            for (int q = 0; q < 4; q++) acc[rg][n][q] = 0.f;
    float accd[RG][4];
#pragma unroll
    for (int rg = 0; rg < RG; rg++)
#pragma unroll
        for (int q = 0; q < 4; q++) accd[rg][q] = 0.f;

    const uint32_t* msrc = g_bits2 + ((size_t)wg0 * N + i0 + t) * 4;

    auto issue = [&](int s, int buf) {
        int j0 = s * 128;
#pragma unroll
        for (int i = 0; i < CPT; i++)
            cpasync16(bofs0 + buf * 16384 + i * 4096,
                      bsrc0 + (size_t)(j0 + i * 32) * ldb);
        if (t < 128 * RG)
            cpasync16(smb + buf * MSKSZ + t * 16, msrc + (size_t)s * N * 4);
        if (t < 32)
            cpasync16(sefb + buf * 512 + t * 16, efbase + s * 512 + t * 16);
    };

    issue(0, 0); cpcommit();
    if (NSTEP > 1) issue(1, 1);
    cpcommit();

#pragma unroll 1
    for (int step = 0; step < NSTEP; step++) {
        int buf = step % 3;
        cpwait1();
        __syncthreads();
        if (step + 2 < NSTEP) issue(step + 2, (step + 2) % 3);
        cpcommit();

        uint32_t pbb = sbb + buf * 16384;
        uint32_t pefb = sefb + buf * 512 + qsel;
        uint4 wq0[RG], wq1[RG];
#pragma unroll
        for (int rg = 0; rg < RG; rg++) {
            uint32_t mrow = smb + buf * MSKSZ
                          + (uint32_t)(warp * 16 * RG + rg * 16 + rq) * 16;
            wq0[rg] = lds128(mrow);
            wq1[rg] = lds128(mrow + 128);
        }
#pragma unroll
        for (int kcp = 0; kcp < 4; kcp++) {
#pragma unroll
            for (int kh = 0; kh < 2; kh++) {
                int kc = kcp * 2 + kh;
                uint4 ef = lds128(pefb + kc * 64);
                uint32_t sh = kh * 16;
                uint32_t A[RG][4];
#pragma unroll
                for (int rg = 0; rg < RG; rg++) {
                    uint32_t w0s = ((&wq0[rg].x)[kcp] >> c0);
                    uint32_t w1s = ((&wq1[rg].x)[kcp] >> c0);
                    A[rg][0] = fragP2(g1a[rg], ef.x, ef.z, (w0s >> sh) & 3u);
                    A[rg][1] = fragP2(g1b[rg], ef.x, ef.z, (w1s >> sh) & 3u);
                    A[rg][2] = fragP2(g1a[rg], ef.y, ef.w, (w0s >> (sh + 8)) & 3u);
                    A[rg][3] = fragP2(g1b[rg], ef.y, ef.w, (w1s >> (sh + 8)) & 3u);
                    mma16816(accd[rg], A[rg][0], A[rg][1], A[rg][2], A[rg][3],
                             ones0, ones0);
                }
#pragma unroll
                for (int np = 0; np < NC / 16; np++) {
                    uint32_t b0, b1, b2, b3;
                    ldsm4t(b0, b1, b2, b3, pbb + bswz[np] + kc * 2048);
#pragma unroll
                    for (int rg = 0; rg < RG; rg++) {
                        mma16816(acc[rg][2 * np], A[rg][0], A[rg][1],
                                 A[rg][2], A[rg][3], b0, b1);
                        mma16816(acc[rg][2 * np + 1], A[rg][0], A[rg][1],
                                 A[rg][2], A[rg][3], b2, b3);
                    }
                }
            }
        }
    }

#pragma unroll
    for (int rg = 0; rg < RG; rg++) {
        int r0 = i0 + warp * 16 * RG + rg * 16 + rq;
        if constexpr (ATOMIC) {
            if ((lane & 3) == 0) {
                atomicAdd(&g_denO[r0],     accd[rg][0]);
                atomicAdd(&g_denO[r0 + 8], accd[rg][2]);
            }
#pragma unroll
            for (int nt = 0; nt < NC / 8; nt++) {
                atomicAdd(&g_numO[r0 * NCLS + nt * 8 + c0],     acc[rg][nt][0]);
                atomicAdd(&g_numO[r0 * NCLS + nt * 8 + c0 + 1], acc[rg][nt][1]);
                atomicAdd(&g_numO[(r0 + 8) * NCLS + nt * 8 + c0],     acc[rg][nt][2]);
                atomicAdd(&g_numO[(r0 + 8) * NCLS + nt * 8 + c0 + 1], acc[rg][nt][3]);
            }
        } else {
            if ((lane & 3) == 0) {
                g_dpart1[(zspl * H + head) * N + r0]     = accd[rg][0];
                g_dpart1[(zspl * H + head) * N + r0 + 8] = accd[rg][2];
            }
            float* po0 = g_part1 + (size_t)zspl * N * FIN
                       + (size_t)r0 * FIN + bcol + c0;
            float* po1 = po0 + 8 * FIN;
#pragma unroll
            for (int nt = 0; nt < NC / 8; nt++) {
                *(float2*)(po0 + nt * 8) = make_float2(acc[rg][nt][0], acc[rg][nt][1]);
                *(float2*)(po1 + nt * 8) = make_float2(acc[rg][nt][2], acc[rg][nt][3]);
            }
        }
    }
}

extern "C" void kernel_launch(void* const* d_in, const int* in_sizes, int n_in,
                              void* d_out, int out_size)
{
    const float* x = nullptr;
    const int* adj = nullptr;
    const float *W_heads = nullptr, *a_heads = nullptr, *W_out = nullptr, *a_out = nullptr;
    for (int i = 0; i < n_in; i++) {
        switch (in_sizes[i]) {
            case N * FIN:      x       = (const float*)d_in[i]; break;
            case 67108864:     adj     = (const int*)  d_in[i]; break;
            case H * FIN * KH: W_heads = (const float*)d_in[i]; break;
            case H * 2 * KH:   a_heads = (const float*)d_in[i]; break;
            case FIN * NCLS:   W_out   = (const float*)d_in[i]; break;
            case 2 * NCLS:     a_out   = (const float*)d_in[i]; break;
        }
    }

    float *whoP, *g1P, *g1oP, *numP, *denP;
    __half *wh16P, *who16P;
    uint8_t *efP, *efoP;
    cudaGetSymbolAddress((void**)&wh16P, g_Wh16);
    cudaGetSymbolAddress((void**)&whoP,  g_Whout);
    cudaGetSymbolAddress((void**)&who16P, g_Whout16);
    cudaGetSymbolAddress((void**)&g1P,  g_G1);
    cudaGetSymbolAddress((void**)&efP,  g_EF);
    cudaGetSymbolAddress((void**)&g1oP, g_G1o);
    cudaGetSymbolAddress((void**)&efoP, g_EFo);
    cudaGetSymbolAddress((void**)&numP, g_numO);
    cudaGetSymbolAddress((void**)&denP, g_denO);

    cudaFuncSetAttribute((const void*)attn_hmma<64, 2, NSPL1, false>,
                         cudaFuncAttributeMaxDynamicSharedMemorySize, ATT_DSMEM);
    cudaFuncSetAttribute((const void*)attn_hmma<16, 1, 16, true>,
                         cudaFuncAttributeMaxDynamicSharedMemorySize, ATT_DSMEM);
    cudaFuncSetAttribute(gemm_hmma_kernel,
                         cudaFuncAttributeMaxDynamicSharedMemorySize, GEMM_DSMEM);
    cudaFuncSetAttribute(gemm16_kernel,
                         cudaFuncAttributeMaxDynamicSharedMemorySize, GEMM_DSMEM);

    pack_adj_kernel<<<4096, 256>>>(adj);
    convert16_kernel<<<2048, 256>>>(x, W_heads, W_out);
    gemm_hmma_kernel<<<dim3(N / 128, H), 256, GEMM_DSMEM>>>(a_heads);
    cudaMemsetAsync(numP, 0, N * NCLS * sizeof(float));
    cudaMemsetAsync(denP, 0, N * sizeof(float));
    cudaMemsetAsync(whoP, 0, N * NCLS * sizeof(float));
    attn_hmma<64, 2, NSPL1, false><<<dim3(N / 256, H, NSPL1), 256, ATT_DSMEM>>>(
        g1P, efP, wh16P, FIN);
    finalize1_kernel<<<(N * FIN + 255) / 256, 256>>>();
    gemm16_kernel<<<dim3(N / 128, FIN / 128), 256, GEMM_DSMEM>>>();
    s_out_kernel<<<N / 8, 256>>>(a_out);
    attn_hmma<16, 1, 16, true><<<dim3(N / 128, 1, 16), 256, ATT_DSMEM>>>(
        g1oP, efoP, who16P, NCLS);
    finalize_kernel<<<(N * NCLS + 255) / 256, 256>>>((float*)d_out);
}